// round 8
// baseline (speedup 1.0000x reference)
#include <cuda_runtime.h>
#include <cstdint>

#define TSTEPS 256
#define HSZ 50
#define ISZ 7
#define EPB 32
#define NTHREADS 512
#define NBLOCKS 128

typedef unsigned long long u64;

// smem layout (float offsets)
#define OFF_WX0 0        // [7][50][4]   1400
#define OFF_WH0 1400     // [50][50][4] 10000
#define OFF_WI1 11400    // [50][50][4] 10000
#define OFF_WH1 21400    // [50][50][4] 10000
#define OFF_B0  31400    // [50][4]       200
#define OFF_B1  31600    // [50][4]       200
#define OFF_WFC 31800    // [7][50]       350
#define OFF_BFC 32152    // [8]             8
#define OFF_XS  32160    // [2][7][32]    448
#define OFF_H0  32608    // [2][50][32]  3200
#define OFF_H1  35808    // [2][50][32]  3200
#define SMEM_FLOATS 39008

__device__ __forceinline__ u64 pk2(float lo, float hi) {
    u64 r; asm("mov.b64 %0,{%1,%2};" : "=l"(r) : "f"(lo), "f"(hi)); return r;
}
__device__ __forceinline__ void upk2(float& lo, float& hi, u64 v) {
    asm("mov.b64 {%0,%1},%2;" : "=f"(lo), "=f"(hi) : "l"(v));
}
__device__ __forceinline__ void fma2(u64& c, u64 a, u64 b) {
    asm("fma.rn.f32x2 %0,%1,%2,%0;" : "+l"(c) : "l"(a), "l"(b));
}

__device__ __forceinline__ float sigm(float v) {
    return __fdividef(1.f, 1.f + __expf(-v));
}
__device__ __forceinline__ float tanh_f(float v) {
    return __fdividef(2.f, 1.f + __expf(-2.f * v)) - 1.f;
}

// N-step matvec accumulate, EPT=4 variant.
// Wp: packed weights [(k*50+j)*4 + gate]; one LDS.128 per k.
// hb: operand base pre-offset by this thread's g*4 (row stride 32 floats);
//     one LDS.128 per k yields 4 elements = 2 u64 pairs.
// acc[gate*2 + p]: pair p covers elements 2p, 2p+1.
template<int N>
__device__ __forceinline__ void mvN(const float* __restrict__ Wp,
                                    const float* __restrict__ hb,
                                    int j, u64 acc[8]) {
    #pragma unroll 10
    for (int k = 0; k < N; k++) {
        const float4 w4 = *reinterpret_cast<const float4*>(Wp + (k * HSZ + j) * 4);
        const u64 wi = pk2(w4.x, w4.x), wf = pk2(w4.y, w4.y);
        const u64 wg = pk2(w4.z, w4.z), wo = pk2(w4.w, w4.w);
        const ulonglong2 hh = *reinterpret_cast<const ulonglong2*>(hb + k * EPB);
        fma2(acc[0], wi, hh.x); fma2(acc[1], wi, hh.y);
        fma2(acc[2], wf, hh.x); fma2(acc[3], wf, hh.y);
        fma2(acc[4], wg, hh.x); fma2(acc[5], wg, hh.y);
        fma2(acc[6], wo, hh.x); fma2(acc[7], wo, hh.y);
    }
}

__device__ __forceinline__ void gates4(const u64 acc[8], float c[4], float hn[4]) {
    #pragma unroll
    for (int p = 0; p < 2; p++) {
        float i0, i1, f0, f1, g0, g1, o0, o1;
        upk2(i0, i1, acc[p]);
        upk2(f0, f1, acc[2 + p]);
        upk2(g0, g1, acc[4 + p]);
        upk2(o0, o1, acc[6 + p]);
        const int e = 2 * p;
        c[e]     = sigm(f0) * c[e]     + sigm(i0) * tanh_f(g0);
        c[e + 1] = sigm(f1) * c[e + 1] + sigm(i1) * tanh_f(g1);
        hn[e]     = sigm(o0) * tanh_f(c[e]);
        hn[e + 1] = sigm(o1) * tanh_f(c[e + 1]);
    }
}

__global__ __launch_bounds__(NTHREADS, 1)
void lstm2_fused_v5(const float* __restrict__ x,
                    const float* __restrict__ w_ih0, const float* __restrict__ w_hh0,
                    const float* __restrict__ b_ih0, const float* __restrict__ b_hh0,
                    const float* __restrict__ w_ih1, const float* __restrict__ w_hh1,
                    const float* __restrict__ b_ih1, const float* __restrict__ b_hh1,
                    const float* __restrict__ w_fc,  const float* __restrict__ b_fc,
                    float* __restrict__ out)
{
    extern __shared__ float sm[];
    const int tid = threadIdx.x;
    const int blk = blockIdx.x;

    // ---- stage weights to shared, packed/transposed [k][j][i,f,g,o] ----
    for (int i = tid; i < HSZ * HSZ * 4; i += NTHREADS) {       // 10000 each
        const int k = i / 200, r = i % 200;
        const int j = r >> 2, gi = r & 3;
        const int src = (gi * HSZ + j) * HSZ + k;
        sm[OFF_WH0 + i] = w_hh0[src];
        sm[OFF_WI1 + i] = w_ih1[src];
        sm[OFF_WH1 + i] = w_hh1[src];
    }
    for (int i = tid; i < ISZ * HSZ * 4; i += NTHREADS) {       // 1400
        const int k = i / 200, r = i % 200;
        const int j = r >> 2, gi = r & 3;
        sm[OFF_WX0 + i] = w_ih0[(gi * HSZ + j) * ISZ + k];
    }
    for (int i = tid; i < 200; i += NTHREADS) {
        const int j = i >> 2, gi = i & 3;
        sm[OFF_B0 + i] = b_ih0[gi * HSZ + j] + b_hh0[gi * HSZ + j];
        sm[OFF_B1 + i] = b_ih1[gi * HSZ + j] + b_hh1[gi * HSZ + j];
    }
    for (int i = tid; i < ISZ * HSZ; i += NTHREADS) sm[OFF_WFC + i] = w_fc[i];
    if (tid < ISZ) sm[OFF_BFC + tid] = b_fc[tid];
    // zero both h buffers
    for (int i = tid; i < 2 * HSZ * EPB; i += NTHREADS) {
        sm[OFF_H0 + i] = 0.f;
        sm[OFF_H1 + i] = 0.f;
    }
    // preload x for t=0 into xs buffer 0: xs[k][e]
    if (tid < ISZ * EPB) {
        const int e = tid & 31, kx = tid >> 5;
        sm[OFF_XS + kx * 32 + e] = x[(size_t)(blk * EPB + e) * (TSTEPS * ISZ) + kx];
    }
    __syncthreads();

    const int j = tid >> 3;          // cell 0..63 (active < 50)
    const int g = tid & 7;           // element group, 4 elems each
    const bool act = (j < HSZ);
    const int go = g * 4;            // element offset within block (16B aligned)

    float4 b0v = make_float4(0.f, 0.f, 0.f, 0.f), b1v = b0v;
    if (act) {
        b0v = *reinterpret_cast<const float4*>(sm + OFF_B0 + j * 4);
        b1v = *reinterpret_cast<const float4*>(sm + OFF_B1 + j * 4);
    }

    // per-step x loader: tid<224, kx = tid>>5, e = tid&31
    const float* xp = x;
    if (tid < EPB * ISZ)
        xp = x + (size_t)(blk * EPB + (tid & 31)) * (TSTEPS * ISZ) + (tid >> 5);

    float c0[4] = {0.f, 0.f, 0.f, 0.f};
    float c1[4] = {0.f, 0.f, 0.f, 0.f};
    u64 acc[8];

    int buf = 0;
    for (int t = 0; t < TSTEPS; t++) {
        // prefetch x_{t+1} (lands during compute)
        float xv = 0.f;
        if (tid < EPB * ISZ && t + 1 < TSTEPS) xv = xp[(t + 1) * ISZ];

        // ---- layer 0 ----
        if (act) {
            acc[0] = acc[1] = pk2(b0v.x, b0v.x);
            acc[2] = acc[3] = pk2(b0v.y, b0v.y);
            acc[4] = acc[5] = pk2(b0v.z, b0v.z);
            acc[6] = acc[7] = pk2(b0v.w, b0v.w);
            mvN<HSZ>(sm + OFF_WH0, sm + OFF_H0 + buf * 1600 + go, j, acc);
            mvN<ISZ>(sm + OFF_WX0, sm + OFF_XS + buf * 224  + go, j, acc);
            float hn[4];
            gates4(acc, c0, hn);
            *reinterpret_cast<float4*>(sm + OFF_H0 + (buf ^ 1) * 1600 + j * EPB + go) =
                make_float4(hn[0], hn[1], hn[2], hn[3]);
        }
        __syncthreads();   // A: new h0 visible

        // ---- layer 1 ----
        if (act) {
            acc[0] = acc[1] = pk2(b1v.x, b1v.x);
            acc[2] = acc[3] = pk2(b1v.y, b1v.y);
            acc[4] = acc[5] = pk2(b1v.z, b1v.z);
            acc[6] = acc[7] = pk2(b1v.w, b1v.w);
            mvN<HSZ>(sm + OFF_WI1, sm + OFF_H0 + (buf ^ 1) * 1600 + go, j, acc);
            mvN<HSZ>(sm + OFF_WH1, sm + OFF_H1 + buf * 1600 + go, j, acc);
            float hn[4];
            gates4(acc, c1, hn);
            *reinterpret_cast<float4*>(sm + OFF_H1 + (buf ^ 1) * 1600 + j * EPB + go) =
                make_float4(hn[0], hn[1], hn[2], hn[3]);
        }
        if (tid < EPB * ISZ) sm[OFF_XS + (buf ^ 1) * 224 + tid] = xv;
        __syncthreads();   // B: new h1 + new x visible
        buf ^= 1;
    }

    // ---- FC head: out[e][j] = b_fc[j] + sum_k w_fc[j][k] * h2[e][k] ----
    if (j < ISZ) {
        const float* h2 = sm + OFF_H1 + buf * 1600 + go;
        const float bv = sm[OFF_BFC + j];
        float s[4] = {bv, bv, bv, bv};
        #pragma unroll 10
        for (int k = 0; k < HSZ; k++) {
            const float wv = sm[OFF_WFC + j * HSZ + k];
            #pragma unroll
            for (int e = 0; e < 4; e++) s[e] = fmaf(wv, h2[k * EPB + e], s[e]);
        }
        #pragma unroll
        for (int e = 0; e < 4; e++)
            out[(size_t)(blk * EPB + go + e) * ISZ + j] = s[e];
    }
}

extern "C" void kernel_launch(void* const* d_in, const int* in_sizes, int n_in,
                              void* d_out, int out_size)
{
    const float* x     = (const float*)d_in[0];
    const float* w_ih0 = (const float*)d_in[1];
    const float* w_hh0 = (const float*)d_in[2];
    const float* b_ih0 = (const float*)d_in[3];
    const float* b_hh0 = (const float*)d_in[4];
    const float* w_ih1 = (const float*)d_in[5];
    const float* w_hh1 = (const float*)d_in[6];
    const float* b_ih1 = (const float*)d_in[7];
    const float* b_hh1 = (const float*)d_in[8];
    const float* w_fc  = (const float*)d_in[9];
    const float* b_fc  = (const float*)d_in[10];
    float* out = (float*)d_out;

    const size_t smem_bytes = SMEM_FLOATS * sizeof(float);
    cudaFuncSetAttribute(lstm2_fused_v5,
                         cudaFuncAttributeMaxDynamicSharedMemorySize,
                         (int)smem_bytes);

    lstm2_fused_v5<<<NBLOCKS, NTHREADS, smem_bytes>>>(
        x, w_ih0, w_hh0, b_ih0, b_hh0,
        w_ih1, w_hh1, b_ih1, b_hh1,
        w_fc, b_fc, out);
}